// round 8
// baseline (speedup 1.0000x reference)
#include <cuda_runtime.h>
#include <cstdint>

// Fused pre-norm attention-downsampling:
//   out[b,s,:] = q[b,s,:] + sum_f (LN(q[b,s]) . LN(k[b,4s+f])) * LN(v[b,4s+f])
// B=4, Sq=2048, Skv=8192, D=1024, factor=4.
// R7: double-buffered cp.async.bulk pipeline. All q/k/v traffic flows
// DRAM -> smem (UBLKCP, no L1tex LDG wavefronts) -> registers (LDS.128),
// then the validated R2 block-per-row math. 4 rows per CTA, 2x36KB buffers,
// 3 CTAs/SM.

#define DD 1024
#define NT 256
#define NW 8
#define FACTOR 4
#define RPB 4
#define LN_EPS 1e-5f
#define SMB 96                      // 8 warps * 12 reduce slots
#define ROW_F4 (DD / 4)             // 256 float4 per logical row
#define BUF_F4 (9 * ROW_F4)         // q + 4k + 4v = 2304 float4 = 36864 B
#define PRE_BYTES (9 * DD * 4)

// ---- batched block reduction of N values (2 barriers) ----
template <int N>
__device__ __forceinline__ void block_reduce(float (&val)[N], float* sm) {
#pragma unroll
    for (int i = 0; i < N; i++) {
#pragma unroll
        for (int o = 16; o; o >>= 1)
            val[i] += __shfl_xor_sync(0xffffffffu, val[i], o);
    }
    const int w = threadIdx.x >> 5;
    const int l = threadIdx.x & 31;
    if (l == 0) {
#pragma unroll
        for (int i = 0; i < N; i++) sm[w * N + i] = val[i];
    }
    __syncthreads();
    if (threadIdx.x < N) {
        float t = 0.f;
#pragma unroll
        for (int j = 0; j < NW; j++) t += sm[j * N + threadIdx.x];
        sm[SMB + threadIdx.x] = t;
    }
    __syncthreads();
#pragma unroll
    for (int i = 0; i < N; i++) val[i] = sm[SMB + i];
}

__device__ __forceinline__ float hsum(const float4 a) {
    return (a.x + a.y) + (a.z + a.w);
}
__device__ __forceinline__ float hsq(const float4 a) {
    return (a.x * a.x + a.y * a.y) + (a.z * a.z + a.w * a.w);
}

// ---- mbarrier / bulk-async helpers ----
__device__ __forceinline__ void mbar_init(uint32_t mbar, uint32_t cnt) {
    asm volatile("mbarrier.init.shared.b64 [%0], %1;" ::"r"(mbar), "r"(cnt)
                 : "memory");
}
__device__ __forceinline__ void mbar_expect_tx(uint32_t mbar, uint32_t bytes) {
    asm volatile("mbarrier.arrive.expect_tx.shared.b64 _, [%0], %1;" ::"r"(mbar),
                 "r"(bytes)
                 : "memory");
}
__device__ __forceinline__ void bulk_g2s(uint32_t dst, const void* src,
                                         uint32_t bytes, uint32_t mbar) {
    asm volatile(
        "cp.async.bulk.shared::cta.global.mbarrier::complete_tx::bytes "
        "[%0], [%1], %2, [%3];" ::"r"(dst),
        "l"(src), "r"(bytes), "r"(mbar)
        : "memory");
}
__device__ __forceinline__ void mbar_wait(uint32_t mbar, uint32_t parity) {
    uint32_t done;
    asm volatile(
        "{\n\t.reg .pred p;\n\t"
        "mbarrier.try_wait.parity.acquire.cta.shared::cta.b64 p, [%1], %2;\n\t"
        "selp.b32 %0, 1, 0, p;\n\t}"
        : "=r"(done)
        : "r"(mbar), "r"(parity)
        : "memory");
    if (!done) {
        asm volatile(
            "{\n\t.reg .pred P1;\n\t"
            "WL_%=:\n\t"
            "mbarrier.try_wait.parity.acquire.cta.shared::cta.b64 P1, [%0], %1;\n\t"
            "@P1 bra.uni WD_%=;\n\t"
            "bra.uni WL_%=;\n\t"
            "WD_%=:\n\t}" ::"r"(mbar),
            "r"(parity)
            : "memory");
    }
}

// ---- validated R2 row math: inputs in registers, writes the row ----
__device__ __forceinline__ void row_math(const float4 qv, const float4 (&kr)[4],
                                         const float4 (&vr)[4], const float4 wv,
                                         const float4 bv, float* sm,
                                         float4* outp, int t) {
    const float invD = 1.0f / (float)DD;

    float r1[10];
    r1[0] = hsum(qv);
    r1[1] = hsq(qv);
#pragma unroll
    for (int f = 0; f < FACTOR; f++) {
        r1[2 + 2 * f] = hsum(kr[f]);
        r1[3 + 2 * f] = hsq(kr[f]);
    }
    block_reduce<10>(r1, sm);

    const float mu = r1[0] * invD;
    const float rs = rsqrtf(fmaf(-mu, mu, r1[1] * invD) + LN_EPS);
    float4 qn;
    qn.x = fmaf((qv.x - mu) * rs, wv.x, bv.x);
    qn.y = fmaf((qv.y - mu) * rs, wv.y, bv.y);
    qn.z = fmaf((qv.z - mu) * rs, wv.z, bv.z);
    qn.w = fmaf((qv.w - mu) * rs, wv.w, bv.w);

    float r2[12];
#pragma unroll
    for (int f = 0; f < FACTOR; f++) {
        const float muk = r1[2 + 2 * f] * invD;
        const float rsk =
            rsqrtf(fmaf(-muk, muk, r1[3 + 2 * f] * invD) + LN_EPS);
        const float4 kv = kr[f];
        const float knx = fmaf((kv.x - muk) * rsk, wv.x, bv.x);
        const float kny = fmaf((kv.y - muk) * rsk, wv.y, bv.y);
        const float knz = fmaf((kv.z - muk) * rsk, wv.z, bv.z);
        const float knw = fmaf((kv.w - muk) * rsk, wv.w, bv.w);
        r2[f] = (knx * qn.x + kny * qn.y) + (knz * qn.z + knw * qn.w);
        r2[4 + f] = hsum(vr[f]);
        r2[8 + f] = hsq(vr[f]);
    }
    block_reduce<12>(r2, sm);

    float4 acc = qv;
#pragma unroll
    for (int f = 0; f < FACTOR; f++) {
        const float wt = r2[f];
        const float muv = r2[4 + f] * invD;
        const float rsv =
            rsqrtf(fmaf(-muv, muv, r2[8 + f] * invD) + LN_EPS);
        const float4 vv = vr[f];
        acc.x = fmaf(wt, fmaf((vv.x - muv) * rsv, wv.x, bv.x), acc.x);
        acc.y = fmaf(wt, fmaf((vv.y - muv) * rsv, wv.y, bv.y), acc.y);
        acc.z = fmaf(wt, fmaf((vv.z - muv) * rsv, wv.z, bv.z), acc.z);
        acc.w = fmaf(wt, fmaf((vv.w - muv) * rsv, wv.w, bv.w), acc.w);
    }
    outp[t] = acc;
}

extern __shared__ float4 dynbuf[];   // 2 * BUF_F4 float4 = 73728 B

// issue the 3 bulk copies for one row into buffer `bp`
__device__ __forceinline__ void prefetch_row(int row, float4* bp,
                                             uint32_t mbar, const float4* q4,
                                             const float4* k4,
                                             const float4* v4) {
    const int b = row >> 11;
    const int s = row & 2047;
    const size_t kvo = ((size_t)b * 8192 + (size_t)s * FACTOR) * ROW_F4;
    mbar_expect_tx(mbar, PRE_BYTES);
    bulk_g2s((uint32_t)__cvta_generic_to_shared(bp), q4 + (size_t)row * ROW_F4,
             DD * 4, mbar);
    bulk_g2s((uint32_t)__cvta_generic_to_shared(bp + ROW_F4), k4 + kvo,
             FACTOR * DD * 4, mbar);
    bulk_g2s((uint32_t)__cvta_generic_to_shared(bp + 5 * ROW_F4), v4 + kvo,
             FACTOR * DD * 4, mbar);
}

__global__ __launch_bounds__(NT, 3) void attn_ds_kernel(
    const float* __restrict__ q, const float* __restrict__ k,
    const float* __restrict__ v, const float* __restrict__ lnw,
    const float* __restrict__ lnb, float* __restrict__ out) {
    __shared__ float sm[SMB + 12];
    __shared__ __align__(8) unsigned long long mbar_s[2];

    const int t = threadIdx.x;
    const int r_base = blockIdx.x * RPB;
    const float4* q4 = (const float4*)q;
    const float4* k4 = (const float4*)k;
    const float4* v4 = (const float4*)v;

    const float4 wv = ((const float4*)lnw)[t];
    const float4 bv = ((const float4*)lnb)[t];

    const uint32_t mb0 = (uint32_t)__cvta_generic_to_shared(&mbar_s[0]);
    const uint32_t mb1 = (uint32_t)__cvta_generic_to_shared(&mbar_s[1]);

    if (t == 0) {
        mbar_init(mb0, 1);
        mbar_init(mb1, 1);
    }
    __syncthreads();
    if (t == 0) {
        prefetch_row(r_base + 0, dynbuf, mb0, q4, k4, v4);
        prefetch_row(r_base + 1, dynbuf + BUF_F4, mb1, q4, k4, v4);
    }

#pragma unroll
    for (int i = 0; i < RPB; i++) {
        const int row = r_base + i;
        const int bufid = i & 1;
        float4* bp = dynbuf + bufid * BUF_F4;
        const uint32_t mb = bufid ? mb1 : mb0;

        mbar_wait(mb, (i >> 1) & 1);

        // smem -> registers (9 conflict-free LDS.128)
        float4 qv = bp[t];
        float4 kr[FACTOR], vr[FACTOR];
#pragma unroll
        for (int f = 0; f < FACTOR; f++) {
            kr[f] = bp[(1 + f) * ROW_F4 + t];
            vr[f] = bp[(5 + f) * ROW_F4 + t];
        }
        __syncthreads();  // all reads done -> buffer reusable

        if (t == 0 && i + 2 < RPB)
            prefetch_row(row + 2, bp, mb, q4, k4, v4);

        row_math(qv, kr, vr, wv, bv, sm,
                 (float4*)out + (size_t)row * ROW_F4, t);
    }
}

extern "C" void kernel_launch(void* const* d_in, const int* in_sizes, int n_in,
                              void* d_out, int out_size) {
    const float* q   = (const float*)d_in[0];  // query     [4,2048,1024]
    const float* k   = (const float*)d_in[1];  // key       [4,8192,1024]
    const float* v   = (const float*)d_in[2];  // value     [4,8192,1024]
    const float* lnw = (const float*)d_in[3];  // ln_weight [1024]
    const float* lnb = (const float*)d_in[4];  // ln_bias   [1024]
    float* out = (float*)d_out;                // [4,2048,1024]

    const int dyn = 2 * BUF_F4 * sizeof(float4);  // 73728 B
    cudaFuncSetAttribute(attn_ds_kernel,
                         cudaFuncAttributeMaxDynamicSharedMemorySize, dyn);
    attn_ds_kernel<<<8192 / RPB, NT, dyn>>>(q, k, v, lnw, lnb, out);
}

// round 9
// speedup vs baseline: 1.5633x; 1.5633x over previous
#include <cuda_runtime.h>

// Fused pre-norm attention-downsampling:
//   out[b,s,:] = q[b,s,:] + sum_f (LN(q[b,s]) . LN(k[b,4s+f])) * LN(v[b,4s+f])
// B=4, Sq=2048, Skv=8192, D=1024, factor=4.
// R8: R2's validated block-per-row design with deferred v loads.
//  - Front-batch only q + 4k (phase 1 inputs).
//  - Each v_f is loaded inside the phase-2 loop right after dot_f kills k_f,
//    cutting peak register residency by ~16 floats.
//  - __launch_bounds__(256,5): 51-reg budget -> 5 CTAs/SM (40 warps, 62.5% occ)
//    to decorrelate load bursts and reduction phases across CTAs.

#define DD 1024
#define NT 256
#define NW 8
#define FACTOR 4
#define LN_EPS 1e-5f
#define SMB 96   // 8 warps * 12 max reduce slots

// Batched block reduction of N values, 2 barriers.
template <int N>
__device__ __forceinline__ void block_reduce(float (&val)[N], float* sm) {
#pragma unroll
    for (int i = 0; i < N; i++) {
#pragma unroll
        for (int o = 16; o; o >>= 1)
            val[i] += __shfl_xor_sync(0xffffffffu, val[i], o);
    }
    const int w = threadIdx.x >> 5;
    const int l = threadIdx.x & 31;
    if (l == 0) {
#pragma unroll
        for (int i = 0; i < N; i++) sm[w * N + i] = val[i];
    }
    __syncthreads();
    if (threadIdx.x < N) {
        float t = 0.f;
#pragma unroll
        for (int j = 0; j < NW; j++) t += sm[j * N + threadIdx.x];
        sm[SMB + threadIdx.x] = t;
    }
    __syncthreads();
#pragma unroll
    for (int i = 0; i < N; i++) val[i] = sm[SMB + i];
}

__device__ __forceinline__ float hsum(const float4 a) {
    return (a.x + a.y) + (a.z + a.w);
}
__device__ __forceinline__ float hsq(const float4 a) {
    return (a.x * a.x + a.y * a.y) + (a.z * a.z + a.w * a.w);
}

__global__ __launch_bounds__(NT, 5) void attn_ds_kernel(
    const float* __restrict__ q, const float* __restrict__ k,
    const float* __restrict__ v, const float* __restrict__ lnw,
    const float* __restrict__ lnb, float* __restrict__ out) {
    __shared__ float sm[SMB + 12];

    const int bid = blockIdx.x;          // b*2048 + s
    const int b = bid >> 11;
    const int s = bid & 2047;
    const int t = threadIdx.x;
    const float invD = 1.0f / (float)DD;

    const float4* q4 = (const float4*)q + (size_t)bid * (DD / 4);
    const size_t kvo = ((size_t)b * 8192 + (size_t)s * FACTOR) * (DD / 4);
    const float4* k4 = (const float4*)k + kvo;
    const float4* v4 = (const float4*)v + kvo;

    // Front-batched loads for phase 1: q + 4k + w/b (7 LDG.128).
    const float4 qv = q4[t];
    const float4 wv = ((const float4*)lnw)[t];
    const float4 bv = ((const float4*)lnb)[t];
    float4 kr[FACTOR];
#pragma unroll
    for (int f = 0; f < FACTOR; f++) kr[f] = k4[f * (DD / 4) + t];

    // ---- Phase 1: q + k stats (10 values, one reduction) ----
    float r1[10];
    r1[0] = hsum(qv);
    r1[1] = hsq(qv);
#pragma unroll
    for (int f = 0; f < FACTOR; f++) {
        r1[2 + 2 * f] = hsum(kr[f]);
        r1[3 + 2 * f] = hsq(kr[f]);
    }
    block_reduce<10>(r1, sm);

    const float mu = r1[0] * invD;
    const float rs = rsqrtf(fmaf(-mu, mu, r1[1] * invD) + LN_EPS);
    float4 qn;
    qn.x = fmaf((qv.x - mu) * rs, wv.x, bv.x);
    qn.y = fmaf((qv.y - mu) * rs, wv.y, bv.y);
    qn.z = fmaf((qv.z - mu) * rs, wv.z, bv.z);
    qn.w = fmaf((qv.w - mu) * rs, wv.w, bv.w);

    // ---- Phase 2: dot partials; v_f loaded as k_f dies ----
    float4 vr[FACTOR];
    float r2[12];
#pragma unroll
    for (int f = 0; f < FACTOR; f++) {
        const float muk = r1[2 + 2 * f] * invD;
        const float rsk =
            rsqrtf(fmaf(-muk, muk, r1[3 + 2 * f] * invD) + LN_EPS);
        const float4 kv = kr[f];
        const float knx = fmaf((kv.x - muk) * rsk, wv.x, bv.x);
        const float kny = fmaf((kv.y - muk) * rsk, wv.y, bv.y);
        const float knz = fmaf((kv.z - muk) * rsk, wv.z, bv.z);
        const float knw = fmaf((kv.w - muk) * rsk, wv.w, bv.w);
        r2[f] = (knx * qn.x + kny * qn.y) + (knz * qn.z + knw * qn.w);
        vr[f] = v4[f * (DD / 4) + t];   // k_f register slots freed -> v_f
    }
#pragma unroll
    for (int f = 0; f < FACTOR; f++) {
        r2[4 + f] = hsum(vr[f]);
        r2[8 + f] = hsq(vr[f]);
    }
    block_reduce<12>(r2, sm);

    // ---- Epilogue: residual + weighted LN(v) ----
    float4 acc = qv;
#pragma unroll
    for (int f = 0; f < FACTOR; f++) {
        const float wt = r2[f];
        const float muv = r2[4 + f] * invD;
        const float rsv =
            rsqrtf(fmaf(-muv, muv, r2[8 + f] * invD) + LN_EPS);
        const float4 vv = vr[f];
        acc.x = fmaf(wt, fmaf((vv.x - muv) * rsv, wv.x, bv.x), acc.x);
        acc.y = fmaf(wt, fmaf((vv.y - muv) * rsv, wv.y, bv.y), acc.y);
        acc.z = fmaf(wt, fmaf((vv.z - muv) * rsv, wv.z, bv.z), acc.z);
        acc.w = fmaf(wt, fmaf((vv.w - muv) * rsv, wv.w, bv.w), acc.w);
    }

    ((float4*)out + (size_t)bid * (DD / 4))[t] = acc;
}

extern "C" void kernel_launch(void* const* d_in, const int* in_sizes, int n_in,
                              void* d_out, int out_size) {
    const float* q   = (const float*)d_in[0];  // query     [4,2048,1024]
    const float* k   = (const float*)d_in[1];  // key       [4,8192,1024]
    const float* v   = (const float*)d_in[2];  // value     [4,8192,1024]
    const float* lnw = (const float*)d_in[3];  // ln_weight [1024]
    const float* lnb = (const float*)d_in[4];  // ln_bias   [1024]
    float* out = (float*)d_out;                // [4,2048,1024]

    attn_ds_kernel<<<4 * 2048, NT>>>(q, k, v, lnw, lnb, out);
}